// round 16
// baseline (speedup 1.0000x reference)
#include <cuda_runtime.h>
#include <cstdint>

// out = chem @ (Wout @ Wv)^T + (Wout @ bv + bout)   (softmax over singleton == 1)
//
// Tensor-core path with PERMUTED fragment maps so all gmem traffic is
// LDG.128/STG.128-coalesced:
//   k-map: fragment k-slot (tid, h, kk) -> M column 4*tid + 2*kk + h
//     => lane's A-fragment = its own 4 consecutive floats of rows grp, grp+8
//        (2 coalesced LDG.128 per lane per 16-row tile, zero shuffles).
//   n-map: D col (nh, n) -> output col 4*(n>>1) + 2*nh + (n&1)
//     => lane's 8 outputs form two contiguous float4 (2 coalesced STG.128).
// M/bias fragments apply the same permutations at init (free).
// 3-term compensated tf32 (x_hi*M_hi + x_hi*M_lo + x_lo*M_hi) -> ~1e-7 rel.
// Persistent grid, 3 CTAs/SM, per-warp 4-buffer pipeline (3 tiles ahead).

#define DIMN 16
#define NCTA 444          // 3 per SM x 148

typedef unsigned int u32;

__device__ __forceinline__ void mma_tf32(float& d0, float& d1, float& d2, float& d3,
                                         u32 a0, u32 a1, u32 a2, u32 a3,
                                         u32 b0, u32 b1) {
    asm("mma.sync.aligned.m16n8k8.row.col.f32.tf32.tf32.f32 "
        "{%0,%1,%2,%3}, {%4,%5,%6,%7}, {%8,%9}, {%0,%1,%2,%3};"
        : "+f"(d0), "+f"(d1), "+f"(d2), "+f"(d3)
        : "r"(a0), "r"(a1), "r"(a2), "r"(a3), "r"(b0), "r"(b1));
}

// Tile = 16 rows = 64 float4 = 1 KB per warp. Lane loads float4 of row grp
// (cols 4tid..4tid+3) and row grp+8: idx4 = T*64 + lane and +32.
template <bool GUARD>
__device__ __forceinline__ void load_tile(float4 v[2], const float4* __restrict__ gin,
                                          int idx4, bool live, int total4) {
    if (!live) return;
    if (GUARD) {
        v[0] = (idx4      < total4) ? __ldcs(&gin[idx4])      : make_float4(0.f,0.f,0.f,0.f);
        v[1] = (idx4 + 32 < total4) ? __ldcs(&gin[idx4 + 32]) : make_float4(0.f,0.f,0.f,0.f);
    } else {
        v[0] = __ldcs(&gin[idx4]);
        v[1] = __ldcs(&gin[idx4 + 32]);
    }
}

template <bool GUARD>
__device__ __forceinline__ void proc_tile(const float4 v[2], float4* __restrict__ gout,
                                          int idx4, int total4,
                                          const u32 bHi[2][2][2],
                                          const u32 bLo[2][2][2],
                                          const float cb[2][2]) {
    // Split the 8 inputs into tf32-exact hi + residual lo.
    const float* vf = (const float*)v;          // vf[0..3]=row grp, vf[4..7]=row grp+8
    u32 ah[8], al[8];
#pragma unroll
    for (int j = 0; j < 8; j++) {
        u32 u = __float_as_uint(vf[j]) & 0xffffe000u;
        ah[j] = u;
        al[j] = __float_as_uint(vf[j] - __uint_as_float(u));
    }

    float d[2][4];
#pragma unroll
    for (int nh = 0; nh < 2; nh++) {
        d[nh][0] = cb[nh][0]; d[nh][1] = cb[nh][1];   // bias seed
        d[nh][2] = cb[nh][0]; d[nh][3] = cb[nh][1];
#pragma unroll
        for (int kk = 0; kk < 2; kk++) {
            // A-frag (k-slot tid -> col 4tid+2kk, slot tid+4 -> +1):
            //   a0 = row grp comp 2kk, a1 = row grp+8 comp 2kk,
            //   a2 = row grp comp 2kk+1, a3 = row grp+8 comp 2kk+1.
            u32 A0 = ah[2 * kk],     A1 = ah[4 + 2 * kk];
            u32 A2 = ah[2 * kk + 1], A3 = ah[4 + 2 * kk + 1];
            u32 L0 = al[2 * kk],     L1 = al[4 + 2 * kk];
            u32 L2 = al[2 * kk + 1], L3 = al[4 + 2 * kk + 1];
            mma_tf32(d[nh][0], d[nh][1], d[nh][2], d[nh][3],
                     A0, A1, A2, A3, bHi[kk][nh][0], bHi[kk][nh][1]);
            mma_tf32(d[nh][0], d[nh][1], d[nh][2], d[nh][3],
                     A0, A1, A2, A3, bLo[kk][nh][0], bLo[kk][nh][1]);
            mma_tf32(d[nh][0], d[nh][1], d[nh][2], d[nh][3],
                     L0, L1, L2, L3, bHi[kk][nh][0], bHi[kk][nh][1]);
        }
    }
    // n-map: lane's outputs = rows grp / grp+8, cols 4tid..4tid+3.
    float4 o0 = make_float4(d[0][0], d[0][1], d[1][0], d[1][1]);   // row grp
    float4 o1 = make_float4(d[0][2], d[0][3], d[1][2], d[1][3]);   // row grp+8
    if (!GUARD || idx4 < total4)      __stcs(&gout[idx4], o0);
    if (!GUARD || idx4 + 32 < total4) __stcs(&gout[idx4 + 32], o1);
}

template <bool GUARD>
__global__ __launch_bounds__(256, 3)
void xattn_kernel(const float4* __restrict__ gin, float4* __restrict__ gout,
                  const float* __restrict__ w_in, const float* __restrict__ b_in,
                  const float* __restrict__ w_out, const float* __restrict__ b_out,
                  int total4, int ntiles) {
    __shared__ float sM[DIMN * DIMN];   // sM[j*16+i] = (Wout @ Wv)[j][i]
    __shared__ float sC[DIMN];          // c = Wout @ bv + bout

    int t = threadIdx.x;
    {   // per-CTA weight folding
        int j = t >> 4, i = t & 15;
        float m = 0.f;
#pragma unroll
        for (int k = 0; k < DIMN; k++)
            m += w_out[j * DIMN + k] * w_in[(2 * DIMN + k) * DIMN + i];  // Wv rows 32..47
        sM[j * DIMN + i] = m;
        if (i == 0) {
            float c = b_out[j];
#pragma unroll
            for (int k = 0; k < DIMN; k++)
                c += w_out[j * DIMN + k] * b_in[2 * DIMN + k];
            sC[j] = c;
        }
    }
    __syncthreads();

    const int lane = t & 31, grp = lane >> 2, tid = lane & 3;

    // B-fragments with permuted maps:
    //   n-slot grp (MMA nh) -> M row 4*(grp>>1) + 2*nh + (grp&1)
    //   k-slot (tid, h, kk) -> M col 4*tid + 2*kk + h
    u32 bHi[2][2][2], bLo[2][2][2];
#pragma unroll
    for (int kk = 0; kk < 2; kk++)
#pragma unroll
        for (int nh = 0; nh < 2; nh++)
#pragma unroll
            for (int h = 0; h < 2; h++) {
                int jr = 4 * (grp >> 1) + 2 * nh + (grp & 1);
                int kc = 4 * tid + 2 * kk + h;
                float m = sM[jr * DIMN + kc];
                u32 u = __float_as_uint(m) & 0xffffe000u;
                bHi[kk][nh][h] = u;
                bLo[kk][nh][h] = __float_as_uint(m - __uint_as_float(u));
            }
    // Bias for D slots: col(nh, 2tid+b) = 4*tid + 2*nh + b.
    float cb[2][2];
#pragma unroll
    for (int nh = 0; nh < 2; nh++) {
        cb[nh][0] = sC[4 * tid + 2 * nh];
        cb[nh][1] = sC[4 * tid + 2 * nh + 1];
    }

    const int W = gridDim.x << 3;              // total warps (persistent)
    int T = (blockIdx.x << 3) + (t >> 5);
    if (T >= ntiles) return;
    int idx = T * 64 + lane;                   // float4 cursor for my tile
    const int step = W * 64;

    float4 v0[2], v1[2], v2[2], v3[2];

    // Prologue: 3 tiles in flight before first compute.
    load_tile<GUARD>(v0, gin, idx,            true,               total4);
    load_tile<GUARD>(v1, gin, idx + step,     T + W     < ntiles, total4);
    load_tile<GUARD>(v2, gin, idx + 2 * step, T + 2 * W < ntiles, total4);

    while (true) {
        load_tile<GUARD>(v3, gin, idx + 3 * step, T + 3 * W < ntiles, total4);
        proc_tile<GUARD>(v0, gout, idx, total4, bHi, bLo, cb);
        T += W; if (T >= ntiles) return; idx += step;

        load_tile<GUARD>(v0, gin, idx + 3 * step, T + 3 * W < ntiles, total4);
        proc_tile<GUARD>(v1, gout, idx, total4, bHi, bLo, cb);
        T += W; if (T >= ntiles) return; idx += step;

        load_tile<GUARD>(v1, gin, idx + 3 * step, T + 3 * W < ntiles, total4);
        proc_tile<GUARD>(v2, gout, idx, total4, bHi, bLo, cb);
        T += W; if (T >= ntiles) return; idx += step;

        load_tile<GUARD>(v2, gin, idx + 3 * step, T + 3 * W < ntiles, total4);
        proc_tile<GUARD>(v3, gout, idx, total4, bHi, bLo, cb);
        T += W; if (T >= ntiles) return; idx += step;
    }
}

extern "C" void kernel_launch(void* const* d_in, const int* in_sizes, int n_in,
                              void* d_out, int out_size) {
    // inputs: 0 fp_16 (unused), 1 chem_16, 2 in_proj_weight, 3 in_proj_bias,
    //         4 out_proj_weight, 5 out_proj_bias
    const float* chem  = (const float*)d_in[1];
    const float* w_in  = (const float*)d_in[2];
    const float* b_in  = (const float*)d_in[3];
    const float* w_out = (const float*)d_in[4];
    const float* b_out = (const float*)d_in[5];

    int total  = in_sizes[1];                  // floats (rows * 16)
    int total4 = total / 4;
    int ntiles = (total + 255) / 256;
    int blocks = (ntiles + 7) / 8;
    if (blocks > NCTA) blocks = NCTA;

    if (total % 256 == 0) {
        xattn_kernel<false><<<blocks, 256>>>((const float4*)chem, (float4*)d_out,
                                             w_in, b_in, w_out, b_out,
                                             total4, ntiles);
    } else {
        xattn_kernel<true><<<blocks, 256>>>((const float4*)chem, (float4*)d_out,
                                            w_in, b_in, w_out, b_out,
                                            total4, ntiles);
    }
}